// round 14
// baseline (speedup 1.0000x reference)
#include <cuda_runtime.h>
#include <cuda_fp16.h>
#include <cstdint>

#define DIM  128
#define NMAX 100000
#define EMAX 1600000
#define LDK  136   // padded k-stride (halves) -> 272B rows, conflict-free ldmatrix

// ---- scratch (__device__ globals: allocation-free rule) ----
__device__ __half g_h16[(size_t)NMAX * DIM];   // h = x@W + b (fp16, 25.6MB)
__device__ __half g_wt16[DIM * LDK];           // W^T fp16 [n][k], padded
__device__ uint2  g_edges[EMAX];               // row-sorted (col, half2(v,v) bits)
__device__ int    g_hist[NMAX];
__device__ int    g_offsets[NMAX + 1];
__device__ int    g_cursor[NMAX];
// decoupled-lookback state (flags zeroed each replay via memset node)
__device__ int    g_scan_flag[128];            // 0=none, 1=agg ready, 2=prefix ready
__device__ int    g_scan_agg[128];
__device__ int    g_scan_pfx[128];

// ---------------------------------------------------------------------------
// MMA helpers (sm_80-class: compile fine for compute_103)
// ---------------------------------------------------------------------------
__device__ __forceinline__ uint32_t smem_u32(const void* p) {
    uint32_t a;
    asm("{ .reg .u64 t; cvta.to.shared.u64 t, %1; cvt.u32.u64 %0, t; }"
        : "=r"(a) : "l"(p));
    return a;
}

#define LDSM4(r0, r1, r2, r3, addr)                                        \
    asm volatile("ldmatrix.sync.aligned.m8n8.x4.shared.b16 {%0,%1,%2,%3}, [%4];" \
                 : "=r"(r0), "=r"(r1), "=r"(r2), "=r"(r3) : "r"(addr))

__device__ __forceinline__ void mma16816(
    float* c, uint32_t a0, uint32_t a1, uint32_t a2, uint32_t a3,
    uint32_t b0, uint32_t b1)
{
    asm volatile(
        "mma.sync.aligned.m16n8k16.row.col.f32.f16.f16.f32 "
        "{%0,%1,%2,%3}, {%4,%5,%6,%7}, {%8,%9}, {%0,%1,%2,%3};"
        : "+f"(c[0]), "+f"(c[1]), "+f"(c[2]), "+f"(c[3])
        : "r"(a0), "r"(a1), "r"(a2), "r"(a3), "r"(b0), "r"(b1));
}

// ---------------------------------------------------------------------------
// W packer: g_wt16[n][k] = fp16(W[k][n])
// ---------------------------------------------------------------------------
__global__ void __launch_bounds__(256) pack_w_kernel(const float* __restrict__ W)
{
    int idx = blockIdx.x * 256 + threadIdx.x;   // 16384
    if (idx < DIM * DIM) {
        int k = idx >> 7, n = idx & 127;
        g_wt16[n * LDK + k] = __float2half_rn(W[k * DIM + n]);
    }
}

// ---------------------------------------------------------------------------
// GEMM via mma.sync: h = x@W + b, fp16 h output.
// ---------------------------------------------------------------------------
#define SM_W_OFF   (DIM * LDK * 2)        // 34816
#define SM_B_OFF   (2 * DIM * LDK * 2)    // 69632
#define GEMM_SMEM  (SM_B_OFF + DIM * 4)   // 70144

__global__ void __launch_bounds__(256, 2) gemm_tc_kernel(
    const float* __restrict__ x, const float* __restrict__ b, int n_rows)
{
    extern __shared__ char smem[];
    __half* sX = (__half*)smem;
    float*  sB = (float*)(smem + SM_B_OFF);

    const int tx   = threadIdx.x;
    const int wid  = tx >> 5, lane = tx & 31;
    const int row0 = blockIdx.x * 128;

    // A fill: fp32 x -> fp16 (packed F2FP), padded row-major
    {
        const float4* X4 = (const float4*)(x + (size_t)row0 * DIM);
        #pragma unroll
        for (int i = 0; i < 16; i++) {
            int idx = tx + 256 * i;            // 4096 float4 = 128 rows x 32
            int r = idx >> 5, c4 = idx & 31;
            float4 v = make_float4(0.f, 0.f, 0.f, 0.f);
            if (row0 + r < n_rows) v = X4[idx];
            __half2 h0 = __float22half2_rn(make_float2(v.x, v.y));
            __half2 h1 = __float22half2_rn(make_float2(v.z, v.w));
            *(uint2*)(sX + r * LDK + c4 * 4) =
                make_uint2(*(uint32_t*)&h0, *(uint32_t*)&h1);
        }
    }
    // B fill: raw copy of pre-packed fp16 W^T
    {
        const uint4* src = (const uint4*)g_wt16;   // 2176 uint4
        uint4* dst = (uint4*)(smem + SM_W_OFF);
        #pragma unroll
        for (int i = 0; i < 9; i++) {
            int idx = tx + 256 * i;
            if (idx < (DIM * LDK * 2) / 16) dst[idx] = src[idx];
        }
    }
    if (tx < DIM) sB[tx] = b[tx];
    __syncthreads();

    const uint32_t base = smem_u32(smem);
    const uint32_t sxa = base + ((wid * 16 + (lane & 15)) * LDK + (lane >> 4) * 8) * 2;
    const uint32_t swa = base + SM_W_OFF + ((lane & 15) * LDK + (lane >> 4) * 8) * 2;

    float acc[16][4];
    #pragma unroll
    for (int j = 0; j < 16; j++)
        #pragma unroll
        for (int q = 0; q < 4; q++) acc[j][q] = 0.f;

    #pragma unroll
    for (int s = 0; s < 8; s++) {
        uint32_t a0, a1, a2, a3;
        LDSM4(a0, a1, a2, a3, sxa + s * 32);
        #pragma unroll
        for (int j = 0; j < 8; j++) {
            uint32_t b0, b1, b2, b3;
            LDSM4(b0, b1, b2, b3, swa + j * (16 * LDK * 2) + s * 32);
            mma16816(acc[2 * j],     a0, a1, a2, a3, b0, b2);
            mma16816(acc[2 * j + 1], a0, a1, a2, a3, b1, b3);
        }
    }

    // epilogue: bias + packed fp32->fp16 store
    {
        int rA = row0 + wid * 16 + (lane >> 2);
        int rB = rA + 8;
        int cb = (lane & 3) * 2;
        #pragma unroll
        for (int jj = 0; jj < 16; jj++) {
            int col = jj * 8 + cb;
            float2 bv = *(float2*)(sB + col);
            if (rA < n_rows) {
                __half2 hv = __float22half2_rn(
                    make_float2(acc[jj][0] + bv.x, acc[jj][1] + bv.y));
                *(__half2*)(g_h16 + (size_t)rA * DIM + col) = hv;
            }
            if (rB < n_rows) {
                __half2 hv = __float22half2_rn(
                    make_float2(acc[jj][2] + bv.x, acc[jj][3] + bv.y));
                *(__half2*)(g_h16 + (size_t)rB * DIM + col) = hv;
            }
        }
    }
}

// ---------------------------------------------------------------------------
// CSR build: hist -> single-pass lookback scan -> permute
// ---------------------------------------------------------------------------
__global__ void __launch_bounds__(256) hist_kernel(const int* __restrict__ rows, int n_edges)
{
    int e = blockIdx.x * blockDim.x + threadIdx.x;
    if (e < n_edges) atomicAdd(&g_hist[rows[e]], 1);
}

__device__ __forceinline__ int block_scan_incl(int v, int* wsum)
{
    int lane = threadIdx.x & 31, wid = threadIdx.x >> 5;
    int incl = v;
    #pragma unroll
    for (int o = 1; o < 32; o <<= 1) {
        int t = __shfl_up_sync(0xffffffffu, incl, o);
        if (lane >= o) incl += t;
    }
    if (lane == 31) wsum[wid] = incl;
    __syncthreads();
    if (wid == 0) {
        int w = wsum[lane];
        #pragma unroll
        for (int o = 1; o < 32; o <<= 1) {
            int t = __shfl_up_sync(0xffffffffu, w, o);
            if (lane >= o) w += t;
        }
        wsum[lane] = w;   // wsum[31] = block total
    }
    __syncthreads();
    if (wid > 0) incl += wsum[wid - 1];
    return incl;
}

// One launch, 98 blocks (all co-resident: <=148 SMs, no lookback deadlock).
__global__ void __launch_bounds__(1024) scan_lookback_kernel(int n, int n_edges)
{
    __shared__ int wsum[32];
    __shared__ int s_pfx;
    const int b = blockIdx.x;
    const int i = b * 1024 + threadIdx.x;

    int v = (i < n) ? g_hist[i] : 0;
    int incl = block_scan_incl(v, wsum);
    int block_total = wsum[31];

    if (threadIdx.x == 0) {
        if (b == 0) {
            g_scan_pfx[0] = block_total;
            __threadfence();
            atomicExch(&g_scan_flag[0], 2);
            s_pfx = 0;
        } else {
            g_scan_agg[b] = block_total;
            __threadfence();
            atomicExch(&g_scan_flag[b], 1);
            int excl = 0;
            for (int j = b - 1; j >= 0; ) {
                int f;
                while ((f = atomicAdd(&g_scan_flag[j], 0)) == 0) { }
                __threadfence();
                if (f == 2) { excl += atomicAdd(&g_scan_pfx[j], 0); break; }
                excl += atomicAdd(&g_scan_agg[j], 0);
                j--;
            }
            g_scan_pfx[b] = excl + block_total;
            __threadfence();
            atomicExch(&g_scan_flag[b], 2);
            s_pfx = excl;
        }
    }
    __syncthreads();

    if (i < n) {
        int o = s_pfx + incl - v;   // global exclusive prefix
        g_offsets[i] = o;
        g_cursor[i]  = o;
    }
    if (b == 0 && threadIdx.x == 0) g_offsets[n] = n_edges;
}

// permute: converts val to packed half2(v,v) once.
__global__ void __launch_bounds__(256) permute_kernel(
    const float* __restrict__ vals, const int* __restrict__ rows,
    const int* __restrict__ cols, int n_edges)
{
    int e = blockIdx.x * blockDim.x + threadIdx.x;
    if (e >= n_edges) return;
    int r = rows[e];
    int p = atomicAdd(&g_cursor[r], 1);
    __half2 hv = __float2half2_rn(vals[e]);
    g_edges[p] = make_uint2((unsigned)cols[e], *(uint32_t*)&hv);
}

// ---------------------------------------------------------------------------
// Aggregate: one warp per row. fp16 gather (uint2 = 4 cols/lane, 256B/edge),
// HFMA2 accumulate over 4-edge groups, flush each group to fp32.
// ---------------------------------------------------------------------------
__global__ void __launch_bounds__(256) aggregate_kernel(
    float4* __restrict__ out, int n_nodes)
{
    int gid  = blockIdx.x * blockDim.x + threadIdx.x;
    int r    = gid >> 5;
    int lane = gid & 31;
    if (r >= n_nodes) return;

    int beg = __ldg(&g_offsets[r]);
    int end = __ldg(&g_offsets[r + 1]);

    const uint2* h2 = (const uint2*)g_h16;   // row stride = 32 uint2 (256B)
    float4 acc = make_float4(0.f, 0.f, 0.f, 0.f);

    int i = beg;
    for (; i + 3 < end; i += 4) {
        uint2 e0 = __ldg(&g_edges[i]);
        uint2 e1 = __ldg(&g_edges[i + 1]);
        uint2 e2 = __ldg(&g_edges[i + 2]);
        uint2 e3 = __ldg(&g_edges[i + 3]);
        uint2 h0 = __ldg(h2 + (size_t)e0.x * 32 + lane);
        uint2 h1 = __ldg(h2 + (size_t)e1.x * 32 + lane);
        uint2 hh2 = __ldg(h2 + (size_t)e2.x * 32 + lane);
        uint2 h3 = __ldg(h2 + (size_t)e3.x * 32 + lane);

        __half2 v0 = *(__half2*)&e0.y;
        __half2 v1 = *(__half2*)&e1.y;
        __half2 v2 = *(__half2*)&e2.y;
        __half2 v3 = *(__half2*)&e3.y;

        __half2 a01 = __hmul2(v0, *(__half2*)&h0.x);
        __half2 a23 = __hmul2(v0, *(__half2*)&h0.y);
        a01 = __hfma2(v1, *(__half2*)&h1.x, a01);
        a23 = __hfma2(v1, *(__half2*)&h1.y, a23);
        a01 = __hfma2(v2, *(__half2*)&hh2.x, a01);
        a23 = __hfma2(v2, *(__half2*)&hh2.y, a23);
        a01 = __hfma2(v3, *(__half2*)&h3.x, a01);
        a23 = __hfma2(v3, *(__half2*)&h3.y, a23);

        float2 f01 = __half22float2(a01);     // 1 F2F per edge amortized
        float2 f23 = __half22float2(a23);
        acc.x += f01.x; acc.y += f01.y;
        acc.z += f23.x; acc.w += f23.y;
    }
    if (i < end) {
        __half2 a01 = __float2half2_rn(0.f);
        __half2 a23 = __float2half2_rn(0.f);
        for (; i < end; i++) {
            uint2 e0 = __ldg(&g_edges[i]);
            uint2 h0 = __ldg(h2 + (size_t)e0.x * 32 + lane);
            __half2 v0 = *(__half2*)&e0.y;
            a01 = __hfma2(v0, *(__half2*)&h0.x, a01);
            a23 = __hfma2(v0, *(__half2*)&h0.y, a23);
        }
        float2 f01 = __half22float2(a01);
        float2 f23 = __half22float2(a23);
        acc.x += f01.x; acc.y += f01.y;
        acc.z += f23.x; acc.w += f23.y;
    }

    out[(size_t)r * 32 + lane] = acc;
}

// ---------------------------------------------------------------------------
// Launch: fork/join two-branch graph; memset nodes for zeroing.
// ---------------------------------------------------------------------------
extern "C" void kernel_launch(void* const* d_in, const int* in_sizes, int n_in,
                              void* d_out, int out_size)
{
    const float* x    = (const float*)d_in[0];
    const float* W    = (const float*)d_in[1];
    const float* b    = (const float*)d_in[2];
    const float* vals = (const float*)d_in[3];
    const int*   rows = (const int*)d_in[4];
    const int*   cols = (const int*)d_in[5];
    float4*      out  = (float4*)d_out;

    const int n_nodes = in_sizes[0] / DIM;
    const int n_edges = in_sizes[3];

    static cudaStream_t sB;
    static cudaEvent_t  evFork, evJoin;
    static void *p_hist = nullptr, *p_flag = nullptr;
    static bool init = false;
    if (!init) {
        cudaFuncSetAttribute(gemm_tc_kernel,
                             cudaFuncAttributeMaxDynamicSharedMemorySize, GEMM_SMEM);
        cudaStreamCreateWithFlags(&sB, cudaStreamNonBlocking);
        cudaEventCreateWithFlags(&evFork, cudaEventDisableTiming);
        cudaEventCreateWithFlags(&evJoin, cudaEventDisableTiming);
        cudaGetSymbolAddress(&p_hist, g_hist);
        cudaGetSymbolAddress(&p_flag, g_scan_flag);
        init = true;
    }

    const int nb = (n_nodes + 1023) / 1024;   // 98 blocks <= 148 SMs

    // fork
    cudaEventRecord(evFork, 0);
    cudaStreamWaitEvent(sB, evFork, 0);

    // branch B: CSR build (memset nodes instead of zero kernels)
    cudaMemsetAsync(p_hist, 0, (size_t)n_nodes * sizeof(int), sB);
    cudaMemsetAsync(p_flag, 0, sizeof(int) * 128, sB);
    hist_kernel<<<(n_edges + 255) / 256, 256, 0, sB>>>(rows, n_edges);
    scan_lookback_kernel<<<nb, 1024, 0, sB>>>(n_nodes, n_edges);
    permute_kernel<<<(n_edges + 255) / 256, 256, 0, sB>>>(vals, rows, cols, n_edges);

    // branch A: pack W (fp16) then HMMA GEMM (fp16 h out)
    pack_w_kernel<<<(DIM * DIM + 255) / 256, 256>>>(W);
    gemm_tc_kernel<<<(n_nodes + 127) / 128, 256, GEMM_SMEM>>>(x, b, n_nodes);

    // join
    cudaEventRecord(evJoin, sB);
    cudaStreamWaitEvent(0, evJoin, 0);

    // aggregate
    {
        long long total_threads = (long long)n_nodes * 32;
        int blocks = (int)((total_threads + 255) / 256);
        aggregate_kernel<<<blocks, 256>>>(out, n_nodes);
    }
}

// round 15
// speedup vs baseline: 1.1140x; 1.1140x over previous
#include <cuda_runtime.h>
#include <cuda_fp16.h>
#include <cstdint>

#define DIM  128
#define NMAX 100000
#define EMAX 1600000
#define LDK  136   // padded k-stride (halves) -> 272B rows, conflict-free ldmatrix

// ---- scratch (__device__ globals: allocation-free rule) ----
__device__ __half g_h16[(size_t)NMAX * DIM];   // h = x@W + b (fp16, 25.6MB)
__device__ __half g_wt16[DIM * LDK];           // W^T fp16 [n][k], padded
__device__ uint2  g_edges[EMAX];               // row-sorted (col, half2(v,v) bits)
__device__ int    g_hist[NMAX];
__device__ int    g_offsets[NMAX + 1];
__device__ int    g_cursor[NMAX];
// decoupled-lookback state (zeroed each replay via memset node)
__device__ int    g_scan_flag[128];            // 0=none, 1=agg ready, 2=prefix ready
__device__ int    g_scan_agg[128];
__device__ int    g_scan_pfx[128];

// ---------------------------------------------------------------------------
// MMA helpers (sm_80-class: compile fine for compute_103)
// ---------------------------------------------------------------------------
__device__ __forceinline__ uint32_t smem_u32(const void* p) {
    uint32_t a;
    asm("{ .reg .u64 t; cvta.to.shared.u64 t, %1; cvt.u32.u64 %0, t; }"
        : "=r"(a) : "l"(p));
    return a;
}

#define LDSM4(r0, r1, r2, r3, addr)                                        \
    asm volatile("ldmatrix.sync.aligned.m8n8.x4.shared.b16 {%0,%1,%2,%3}, [%4];" \
                 : "=r"(r0), "=r"(r1), "=r"(r2), "=r"(r3) : "r"(addr))

__device__ __forceinline__ void mma16816(
    float* c, uint32_t a0, uint32_t a1, uint32_t a2, uint32_t a3,
    uint32_t b0, uint32_t b1)
{
    asm volatile(
        "mma.sync.aligned.m16n8k16.row.col.f32.f16.f16.f32 "
        "{%0,%1,%2,%3}, {%4,%5,%6,%7}, {%8,%9}, {%0,%1,%2,%3};"
        : "+f"(c[0]), "+f"(c[1]), "+f"(c[2]), "+f"(c[3])
        : "r"(a0), "r"(a1), "r"(a2), "r"(a3), "r"(b0), "r"(b1));
}

// ---------------------------------------------------------------------------
// W packer: g_wt16[n][k] = fp16(W[k][n])
// ---------------------------------------------------------------------------
__global__ void __launch_bounds__(256) pack_w_kernel(const float* __restrict__ W)
{
    int idx = blockIdx.x * 256 + threadIdx.x;   // 16384
    if (idx < DIM * DIM) {
        int k = idx >> 7, n = idx & 127;
        g_wt16[n * LDK + k] = __float2half_rn(W[k * DIM + n]);
    }
}

// ---------------------------------------------------------------------------
// GEMM via mma.sync: h = x@W + b, fp16 h output.
// ---------------------------------------------------------------------------
#define SM_W_OFF   (DIM * LDK * 2)        // 34816
#define SM_B_OFF   (2 * DIM * LDK * 2)    // 69632
#define GEMM_SMEM  (SM_B_OFF + DIM * 4)   // 70144

__global__ void __launch_bounds__(256, 2) gemm_tc_kernel(
    const float* __restrict__ x, const float* __restrict__ b, int n_rows)
{
    extern __shared__ char smem[];
    __half* sX = (__half*)smem;
    float*  sB = (float*)(smem + SM_B_OFF);

    const int tx   = threadIdx.x;
    const int wid  = tx >> 5, lane = tx & 31;
    const int row0 = blockIdx.x * 128;

    // A fill: fp32 x -> fp16 (packed F2FP), padded row-major
    {
        const float4* X4 = (const float4*)(x + (size_t)row0 * DIM);
        #pragma unroll
        for (int i = 0; i < 16; i++) {
            int idx = tx + 256 * i;            // 4096 float4 = 128 rows x 32
            int r = idx >> 5, c4 = idx & 31;
            float4 v = make_float4(0.f, 0.f, 0.f, 0.f);
            if (row0 + r < n_rows) v = X4[idx];
            __half2 h0 = __float22half2_rn(make_float2(v.x, v.y));
            __half2 h1 = __float22half2_rn(make_float2(v.z, v.w));
            *(uint2*)(sX + r * LDK + c4 * 4) =
                make_uint2(*(uint32_t*)&h0, *(uint32_t*)&h1);
        }
    }
    // B fill: raw copy of pre-packed fp16 W^T
    {
        const uint4* src = (const uint4*)g_wt16;   // 2176 uint4
        uint4* dst = (uint4*)(smem + SM_W_OFF);
        #pragma unroll
        for (int i = 0; i < 9; i++) {
            int idx = tx + 256 * i;
            if (idx < (DIM * LDK * 2) / 16) dst[idx] = src[idx];
        }
    }
    if (tx < DIM) sB[tx] = b[tx];
    __syncthreads();

    const uint32_t base = smem_u32(smem);
    const uint32_t sxa = base + ((wid * 16 + (lane & 15)) * LDK + (lane >> 4) * 8) * 2;
    const uint32_t swa = base + SM_W_OFF + ((lane & 15) * LDK + (lane >> 4) * 8) * 2;

    float acc[16][4];
    #pragma unroll
    for (int j = 0; j < 16; j++)
        #pragma unroll
        for (int q = 0; q < 4; q++) acc[j][q] = 0.f;

    #pragma unroll
    for (int s = 0; s < 8; s++) {
        uint32_t a0, a1, a2, a3;
        LDSM4(a0, a1, a2, a3, sxa + s * 32);
        #pragma unroll
        for (int j = 0; j < 8; j++) {
            uint32_t b0, b1, b2, b3;
            LDSM4(b0, b1, b2, b3, swa + j * (16 * LDK * 2) + s * 32);
            mma16816(acc[2 * j],     a0, a1, a2, a3, b0, b2);
            mma16816(acc[2 * j + 1], a0, a1, a2, a3, b1, b3);
        }
    }

    // epilogue: bias + packed fp32->fp16 store
    {
        int rA = row0 + wid * 16 + (lane >> 2);
        int rB = rA + 8;
        int cb = (lane & 3) * 2;
        #pragma unroll
        for (int jj = 0; jj < 16; jj++) {
            int col = jj * 8 + cb;
            float2 bv = *(float2*)(sB + col);
            if (rA < n_rows) {
                __half2 hv = __float22half2_rn(
                    make_float2(acc[jj][0] + bv.x, acc[jj][1] + bv.y));
                *(__half2*)(g_h16 + (size_t)rA * DIM + col) = hv;
            }
            if (rB < n_rows) {
                __half2 hv = __float22half2_rn(
                    make_float2(acc[jj][2] + bv.x, acc[jj][3] + bv.y));
                *(__half2*)(g_h16 + (size_t)rB * DIM + col) = hv;
            }
        }
    }
}

// ---------------------------------------------------------------------------
// CSR build: hist -> single-pass lookback scan (WARP-PARALLEL) -> permute
// ---------------------------------------------------------------------------
__global__ void __launch_bounds__(256) hist_kernel(const int* __restrict__ rows, int n_edges)
{
    int e = blockIdx.x * blockDim.x + threadIdx.x;
    if (e < n_edges) atomicAdd(&g_hist[rows[e]], 1);
}

__device__ __forceinline__ int block_scan_incl(int v, int* wsum)
{
    int lane = threadIdx.x & 31, wid = threadIdx.x >> 5;
    int incl = v;
    #pragma unroll
    for (int o = 1; o < 32; o <<= 1) {
        int t = __shfl_up_sync(0xffffffffu, incl, o);
        if (lane >= o) incl += t;
    }
    if (lane == 31) wsum[wid] = incl;
    __syncthreads();
    if (wid == 0) {
        int w = wsum[lane];
        #pragma unroll
        for (int o = 1; o < 32; o <<= 1) {
            int t = __shfl_up_sync(0xffffffffu, w, o);
            if (lane >= o) w += t;
        }
        wsum[lane] = w;   // wsum[31] = block total
    }
    __syncthreads();
    if (wid > 0) incl += wsum[wid - 1];
    return incl;
}

// One launch, 98 blocks (all co-resident on 148 SMs -> progress guaranteed).
// Warp-parallel lookback: 32 predecessors per window, <=4 windows.
__global__ void __launch_bounds__(1024) scan_lookback_kernel(int n, int n_edges)
{
    __shared__ int wsum[32];
    __shared__ int s_pfx;
    const int b = blockIdx.x;
    const int i = b * 1024 + threadIdx.x;
    const int lane = threadIdx.x & 31;

    int v = (i < n) ? g_hist[i] : 0;
    int incl = block_scan_incl(v, wsum);
    int block_total = wsum[31];

    if (threadIdx.x < 32) {
        if (b == 0) {
            if (lane == 0) {
                g_scan_pfx[0] = block_total;
                __threadfence();
                atomicExch(&g_scan_flag[0], 2);
                s_pfx = 0;
            }
        } else {
            // publish aggregate early so successors can proceed
            if (lane == 0) {
                g_scan_agg[b] = block_total;
                __threadfence();
                atomicExch(&g_scan_flag[b], 1);
            }
            int excl = 0;
            int j = b - 1 - lane;            // lane 0 = nearest predecessor
            while (true) {
                int f = 0, a = 0;
                if (j >= 0) {
                    do { f = atomicAdd(&g_scan_flag[j], 0); } while (f == 0);
                    __threadfence();
                    a = (f == 2) ? atomicAdd(&g_scan_pfx[j], 0)
                                 : atomicAdd(&g_scan_agg[j], 0);
                }
                unsigned dm = __ballot_sync(0xffffffffu, (j >= 0) && (f == 2));
                if (dm) {
                    int first = __ffs(dm) - 1;       // nearest lane with full prefix
                    int c = (j >= 0 && lane <= first) ? a : 0;
                    #pragma unroll
                    for (int o = 16; o; o >>= 1) c += __shfl_down_sync(0xffffffffu, c, o);
                    if (lane == 0) excl += c;
                    break;
                } else {
                    int c = (j >= 0) ? a : 0;
                    #pragma unroll
                    for (int o = 16; o; o >>= 1) c += __shfl_down_sync(0xffffffffu, c, o);
                    if (lane == 0) excl += c;
                    j -= 32;
                }
            }
            if (lane == 0) {
                g_scan_pfx[b] = excl + block_total;
                __threadfence();
                atomicExch(&g_scan_flag[b], 2);
                s_pfx = excl;
            }
        }
    }
    __syncthreads();

    if (i < n) {
        int o = s_pfx + incl - v;   // global exclusive prefix
        g_offsets[i] = o;
        g_cursor[i]  = o;
    }
    if (b == 0 && threadIdx.x == 0) g_offsets[n] = n_edges;
}

// permute: converts val to packed half2(v,v) once.
__global__ void __launch_bounds__(256) permute_kernel(
    const float* __restrict__ vals, const int* __restrict__ rows,
    const int* __restrict__ cols, int n_edges)
{
    int e = blockIdx.x * blockDim.x + threadIdx.x;
    if (e >= n_edges) return;
    int r = rows[e];
    int p = atomicAdd(&g_cursor[r], 1);
    __half2 hv = __float2half2_rn(vals[e]);
    g_edges[p] = make_uint2((unsigned)cols[e], *(uint32_t*)&hv);
}

// ---------------------------------------------------------------------------
// Aggregate: one warp per row. fp16 gather (uint2 = 4 cols/lane, 256B/edge),
// HFMA2 accumulate over 4-edge groups, flush each group to fp32.
// ---------------------------------------------------------------------------
__global__ void __launch_bounds__(256) aggregate_kernel(
    float4* __restrict__ out, int n_nodes)
{
    int gid  = blockIdx.x * blockDim.x + threadIdx.x;
    int r    = gid >> 5;
    int lane = gid & 31;
    if (r >= n_nodes) return;

    int beg = __ldg(&g_offsets[r]);
    int end = __ldg(&g_offsets[r + 1]);

    const uint2* h2 = (const uint2*)g_h16;   // row stride = 32 uint2 (256B)
    float4 acc = make_float4(0.f, 0.f, 0.f, 0.f);

    int i = beg;
    for (; i + 3 < end; i += 4) {
        uint2 e0 = __ldg(&g_edges[i]);
        uint2 e1 = __ldg(&g_edges[i + 1]);
        uint2 e2 = __ldg(&g_edges[i + 2]);
        uint2 e3 = __ldg(&g_edges[i + 3]);
        uint2 h0 = __ldg(h2 + (size_t)e0.x * 32 + lane);
        uint2 h1 = __ldg(h2 + (size_t)e1.x * 32 + lane);
        uint2 hh2 = __ldg(h2 + (size_t)e2.x * 32 + lane);
        uint2 h3 = __ldg(h2 + (size_t)e3.x * 32 + lane);

        __half2 v0 = *(__half2*)&e0.y;
        __half2 v1 = *(__half2*)&e1.y;
        __half2 v2 = *(__half2*)&e2.y;
        __half2 v3 = *(__half2*)&e3.y;

        __half2 a01 = __hmul2(v0, *(__half2*)&h0.x);
        __half2 a23 = __hmul2(v0, *(__half2*)&h0.y);
        a01 = __hfma2(v1, *(__half2*)&h1.x, a01);
        a23 = __hfma2(v1, *(__half2*)&h1.y, a23);
        a01 = __hfma2(v2, *(__half2*)&hh2.x, a01);
        a23 = __hfma2(v2, *(__half2*)&hh2.y, a23);
        a01 = __hfma2(v3, *(__half2*)&h3.x, a01);
        a23 = __hfma2(v3, *(__half2*)&h3.y, a23);

        float2 f01 = __half22float2(a01);     // 1 F2F per edge amortized
        float2 f23 = __half22float2(a23);
        acc.x += f01.x; acc.y += f01.y;
        acc.z += f23.x; acc.w += f23.y;
    }
    if (i < end) {
        __half2 a01 = __float2half2_rn(0.f);
        __half2 a23 = __float2half2_rn(0.f);
        for (; i < end; i++) {
            uint2 e0 = __ldg(&g_edges[i]);
            uint2 h0 = __ldg(h2 + (size_t)e0.x * 32 + lane);
            __half2 v0 = *(__half2*)&e0.y;
            a01 = __hfma2(v0, *(__half2*)&h0.x, a01);
            a23 = __hfma2(v0, *(__half2*)&h0.y, a23);
        }
        float2 f01 = __half22float2(a01);
        float2 f23 = __half22float2(a23);
        acc.x += f01.x; acc.y += f01.y;
        acc.z += f23.x; acc.w += f23.y;
    }

    out[(size_t)r * 32 + lane] = acc;
}

// ---------------------------------------------------------------------------
// Launch: fork/join two-branch graph; memset nodes for zeroing.
// ---------------------------------------------------------------------------
extern "C" void kernel_launch(void* const* d_in, const int* in_sizes, int n_in,
                              void* d_out, int out_size)
{
    const float* x    = (const float*)d_in[0];
    const float* W    = (const float*)d_in[1];
    const float* b    = (const float*)d_in[2];
    const float* vals = (const float*)d_in[3];
    const int*   rows = (const int*)d_in[4];
    const int*   cols = (const int*)d_in[5];
    float4*      out  = (float4*)d_out;

    const int n_nodes = in_sizes[0] / DIM;
    const int n_edges = in_sizes[3];

    static cudaStream_t sB;
    static cudaEvent_t  evFork, evJoin;
    static void *p_hist = nullptr, *p_flag = nullptr;
    static bool init = false;
    if (!init) {
        cudaFuncSetAttribute(gemm_tc_kernel,
                             cudaFuncAttributeMaxDynamicSharedMemorySize, GEMM_SMEM);
        cudaStreamCreateWithFlags(&sB, cudaStreamNonBlocking);
        cudaEventCreateWithFlags(&evFork, cudaEventDisableTiming);
        cudaEventCreateWithFlags(&evJoin, cudaEventDisableTiming);
        cudaGetSymbolAddress(&p_hist, g_hist);
        cudaGetSymbolAddress(&p_flag, g_scan_flag);
        init = true;
    }

    const int nb = (n_nodes + 1023) / 1024;   // 98 blocks <= 148 SMs

    // fork
    cudaEventRecord(evFork, 0);
    cudaStreamWaitEvent(sB, evFork, 0);

    // branch B: CSR build
    cudaMemsetAsync(p_hist, 0, (size_t)n_nodes * sizeof(int), sB);
    cudaMemsetAsync(p_flag, 0, sizeof(int) * 128, sB);
    hist_kernel<<<(n_edges + 255) / 256, 256, 0, sB>>>(rows, n_edges);
    scan_lookback_kernel<<<nb, 1024, 0, sB>>>(n_nodes, n_edges);
    permute_kernel<<<(n_edges + 255) / 256, 256, 0, sB>>>(vals, rows, cols, n_edges);

    // branch A: pack W (fp16) then HMMA GEMM (fp16 h out)
    pack_w_kernel<<<(DIM * DIM + 255) / 256, 256>>>(W);
    gemm_tc_kernel<<<(n_nodes + 127) / 128, 256, GEMM_SMEM>>>(x, b, n_nodes);

    // join
    cudaEventRecord(evJoin, sB);
    cudaStreamWaitEvent(0, evJoin, 0);

    // aggregate
    {
        long long total_threads = (long long)n_nodes * 32;
        int blocks = (int)((total_threads + 255) / 256);
        aggregate_kernel<<<blocks, 256>>>(out, n_nodes);
    }
}